// round 15
// baseline (speedup 1.0000x reference)
#include <cuda_runtime.h>
#include <cuda_fp16.h>
#include <cstdint>

// ============================================================================
// UniversalKANLinear: out[b,o] = sum_k (softplus(x[b,k])-ln2) * W[o,k]
//                              + (softplus(1)-ln2) * W[o,2048]
// B=8192, K=2048, N=2048.
// R15: WARP SPECIALIZATION. All previous configs plateaued at tensor~70%
//      because math warps issue their own cp.async bursts (LSU rt=8/op)
//      and stall ~100-400cyc/iter on the LSU dispatch queue, starving MMA
//      issue. Now: 4 consumer warps (pure LDSM+MMA, zero LSU) + 2 producer
//      warps (all cp.async), synced by named barriers (FULL 1..3 / EMPTY
//      4..6, count=192). CTA 128x64x64, 3 stages, 72KB -> 3 CTAs/SM.
// ============================================================================

#define BATCH_M 8192
#define DIM_K   2048
#define DIM_N   2048
#define W_COLS  2049

#define BM 128
#define BN 64
#define BK 64
#define KITERS (DIM_K / BK)     // 32
#define STAGES 3

#define A_STAGE_BYTES (BM * 128)                 // 16384
#define B_STAGE_BYTES (BN * 128)                 // 8192
#define STAGE_BYTES   (A_STAGE_BYTES + B_STAGE_BYTES)  // 24576
#define SMEM_BYTES    (STAGES * STAGE_BYTES)           // 73728

#define NTHREADS 192          // 4 consumer warps + 2 producer warps
#define BAR_CNT  192

#define C_BIAS 0.62011450695827751f   // softplus(1) - ln2
#define LN2F   0.69314718055994531f

// prep grid layout
#define NX_BLOCKS 8192    // x: 8192 blocks x 256 thr x 2 float4
#define NW_BLOCKS 4096    // W: 4096 blocks x 256 thr x 4 scalars

// ---------------- scratch (device globals: allocation-free rule) -----------
__device__ __align__(1024) __half g_A[(size_t)BATCH_M * DIM_K];  // 32 MB phi(x)
__device__ __align__(1024) __half g_B[(size_t)DIM_N * DIM_K];    // 8 MB W
__device__ __align__(128)  float  g_bias[DIM_N];

// ---------------- helpers ---------------------------------------------------
__device__ __forceinline__ uint32_t smem_u32(const void* p) {
    uint32_t a;
    asm("{ .reg .u64 t; cvta.to.shared.u64 t, %1; cvt.u32.u64 %0, t; }" : "=r"(a) : "l"(p));
    return a;
}

#define CP_ASYNC16(dst_u32, src_ptr) \
    asm volatile("cp.async.cg.shared.global [%0], [%1], 16;" \
                 :: "r"(dst_u32), "l"(src_ptr) : "memory")
#define CP_COMMIT() asm volatile("cp.async.commit_group;" ::: "memory")
#define CP_WAIT(N)  asm volatile("cp.async.wait_group %0;" :: "n"(N) : "memory")

#define BAR_SYNC(id)   asm volatile("bar.sync %0, %1;"   :: "r"(id), "n"(BAR_CNT) : "memory")
#define BAR_ARRIVE(id) asm volatile("bar.arrive %0, %1;" :: "r"(id), "n"(BAR_CNT) : "memory")

#define LDMATRIX_X4(r0, r1, r2, r3, addr) \
    asm volatile("ldmatrix.sync.aligned.m8n8.x4.shared.b16 {%0,%1,%2,%3}, [%4];" \
                 : "=r"(r0), "=r"(r1), "=r"(r2), "=r"(r3) : "r"(addr))

#define MMA_F16(c, a0, a1, a2, a3, b0, b1) \
    asm volatile("mma.sync.aligned.m16n8k16.row.col.f32.f16.f16.f32 " \
                 "{%0,%1,%2,%3}, {%4,%5,%6,%7}, {%8,%9}, {%0,%1,%2,%3};" \
                 : "+f"((c)[0]), "+f"((c)[1]), "+f"((c)[2]), "+f"((c)[3]) \
                 : "r"(a0), "r"(a1), "r"(a2), "r"(a3), "r"(b0), "r"(b1))

// ---------------- fused pre-pass kernel -------------------------------------
__device__ __forceinline__ float phi_f(float x) {
    float t = __expf(-fabsf(x));
    return fmaxf(x, 0.0f) + __logf(1.0f + t) - LN2F;
}

__device__ __forceinline__ uint2 phi_pack(float4 v) {
    __half2 h0 = __floats2half2_rn(phi_f(v.x), phi_f(v.y));
    __half2 h1 = __floats2half2_rn(phi_f(v.z), phi_f(v.w));
    uint2 p;
    p.x = *reinterpret_cast<uint32_t*>(&h0);
    p.y = *reinterpret_cast<uint32_t*>(&h1);
    return p;
}

__global__ void __launch_bounds__(256)
prep_fused_kernel(const float* __restrict__ x, const float* __restrict__ W) {
    const int b = blockIdx.x;
    const int tid = threadIdx.x;
    if (b < NX_BLOCKS) {
        size_t i = (size_t)b * 512 + tid;
        float4 v0 = reinterpret_cast<const float4*>(x)[i];
        float4 v1 = reinterpret_cast<const float4*>(x)[i + 256];
        reinterpret_cast<uint2*>(g_A)[i]       = phi_pack(v0);
        reinterpret_cast<uint2*>(g_A)[i + 256] = phi_pack(v1);
    } else {
        const int wb = b - NX_BLOCKS;
        size_t base = (size_t)wb * 1024 + tid * 4;
        int o = (int)(base >> 11);
        int k = (int)(base & 2047);
        const float* wr = W + (size_t)o * W_COLS + k;
        __half2 h0 = __floats2half2_rn(wr[0], wr[1]);
        __half2 h1 = __floats2half2_rn(wr[2], wr[3]);
        uint2 pack;
        pack.x = *reinterpret_cast<uint32_t*>(&h0);
        pack.y = *reinterpret_cast<uint32_t*>(&h1);
        *reinterpret_cast<uint2*>(g_B + base) = pack;
        if (wb == 0) {
            for (int o2 = tid; o2 < DIM_N; o2 += 256)
                g_bias[o2] = C_BIAS * W[(size_t)o2 * W_COLS + (W_COLS - 1)];
        }
    }
}

// ---------------- GEMM kernel (warp-specialized) ----------------------------
// smem addr for (row, 16B-chunk c16): row*128 + (c16 ^ (row&7))*16
__global__ void __launch_bounds__(NTHREADS, 3)
kan_gemm_kernel(float* __restrict__ out) {
    extern __shared__ char smem[];
    const uint32_t sbase = smem_u32(smem);
    const int tid = threadIdx.x;
    const int lane = tid & 31;
    const int wid = tid >> 5;          // 0..5
    const int m0 = blockIdx.x * BM;
    const int n0 = blockIdx.y * BN;

    if (wid >= 4) {
        // ================= PRODUCER warps (wid 4,5): all cp.async ==========
        const int p = wid - 4;                     // 0 or 1
        // each producer covers 768 of the 1536 16B chunks per stage:
        // combined chunk index v in [0,1536): v<1024 -> A, else B.
        auto copy_part = [&](int s, int kt) {
            const uint32_t sA = sbase + (uint32_t)s * STAGE_BYTES;
            const uint32_t sB = sA + A_STAGE_BYTES;
            const __half* gA = g_A + (size_t)m0 * DIM_K + (size_t)kt * BK;
            const __half* gB = g_B + (size_t)n0 * DIM_K + (size_t)kt * BK;
            #pragma unroll
            for (int i = 0; i < 24; i++) {
                int v = p * 32 + lane + i * 64;    // stride 64 over 2 warps
                if (v < 1024) {
                    int row = v >> 3, c16 = v & 7;
                    CP_ASYNC16(sA + row * 128 + ((c16 ^ (row & 7)) * 16),
                               gA + (size_t)row * DIM_K + c16 * 8);
                } else {
                    int u = v - 1024;
                    int row = u >> 3, c16 = u & 7;
                    CP_ASYNC16(sB + row * 128 + ((c16 ^ (row & 7)) * 16),
                               gB + (size_t)row * DIM_K + c16 * 8);
                }
            }
        };

        copy_part(0, 0); CP_COMMIT();
        copy_part(1, 1); CP_COMMIT();
        copy_part(2, 2); CP_COMMIT();
        CP_WAIT(2); BAR_ARRIVE(1);                 // FULL(0)
        CP_WAIT(1); BAR_ARRIVE(2);                 // FULL(1)
        for (int kt = 3; kt < KITERS; kt++) {
            const int s = kt % 3;
            BAR_SYNC(4 + s);                       // EMPTY(s): consumers freed it
            copy_part(s, kt); CP_COMMIT();
            CP_WAIT(1);                            // stage of iter kt-1 landed
            BAR_ARRIVE(1 + ((kt - 1) % 3));        // FULL(kt-1)
        }
        CP_WAIT(0);
        BAR_ARRIVE(1 + ((KITERS - 1) % 3));        // FULL(last)
        return;                                    // producers done
    }

    // ================= CONSUMER warps (wid 0..3): pure LDSM+MMA =============
    const int wm = wid & 1;            // 2 warp rows over BM=128 (64 each)
    const int wn = wid >> 1;           // 2 warp cols over BN=64 (32 each)
    const int r = lane >> 2;           // 0..7
    const int c = lane & 3;            // 0..3

    float acc[4][4][4];
    #pragma unroll
    for (int mt = 0; mt < 4; mt++)
        #pragma unroll
        for (int nt = 0; nt < 4; nt++)
            #pragma unroll
            for (int i = 0; i < 4; i++) acc[mt][nt][i] = 0.0f;

    // ldmatrix lane roles (loop-invariant)
    const int a_row = (lane & 15);                       // row within 16-row tile
    const int a_ch  = (lane >> 4);                       // k16 half (16B chunk)
    const int b_nrow = ((lane >> 4) << 3) + (lane & 7);  // 0-7 then 8-15
    const int b_ch  = (lane >> 3) & 1;                   // k-chunk within k16

    for (int kt = 0; kt < KITERS; kt++) {
        const int s = kt % 3;
        BAR_SYNC(1 + s);                           // FULL(s): stage ready

        const uint32_t sA = sbase + (uint32_t)s * STAGE_BYTES + (wm * 64) * 128;
        const uint32_t sB = sbase + (uint32_t)s * STAGE_BYTES + A_STAGE_BYTES
                            + (wn * 32) * 128;

        #pragma unroll
        for (int ks = 0; ks < 4; ks++) {           // 4 x k16 steps over BK=64
            uint32_t a[4][4], b[2][4];
            #pragma unroll
            for (int mt = 0; mt < 4; mt++) {
                int row = mt * 16 + a_row;
                int ch = ks * 2 + a_ch;
                uint32_t addr = sA + row * 128 + ((ch ^ (row & 7)) * 16);
                LDMATRIX_X4(a[mt][0], a[mt][1], a[mt][2], a[mt][3], addr);
            }
            #pragma unroll
            for (int np = 0; np < 2; np++) {       // 2 x 16 n-rows = 32 cols
                int row = np * 16 + b_nrow;
                int ch = ks * 2 + b_ch;
                uint32_t addr = sB + row * 128 + ((ch ^ (row & 7)) * 16);
                LDMATRIX_X4(b[np][0], b[np][1], b[np][2], b[np][3], addr);
            }
            #pragma unroll
            for (int mt = 0; mt < 4; mt++) {
                #pragma unroll
                for (int np = 0; np < 2; np++) {
                    MMA_F16(acc[mt][2 * np],     a[mt][0], a[mt][1], a[mt][2], a[mt][3],
                            b[np][0], b[np][1]);
                    MMA_F16(acc[mt][2 * np + 1], a[mt][0], a[mt][1], a[mt][2], a[mt][3],
                            b[np][2], b[np][3]);
                }
            }
        }

        BAR_ARRIVE(4 + s);                         // EMPTY(s): done reading
    }

    // ---- epilogue: acc + bias -> out ----
    const int mbase = m0 + wm * 64;
    const int nbase = n0 + wn * 32;
    #pragma unroll
    for (int mt = 0; mt < 4; mt++) {
        #pragma unroll
        for (int nt = 0; nt < 4; nt++) {
            int mrow = mbase + mt * 16 + r;
            int ncol = nbase + nt * 8 + 2 * c;
            float2 bv = *reinterpret_cast<const float2*>(g_bias + ncol);
            float2 v0, v1;
            v0.x = acc[mt][nt][0] + bv.x;
            v0.y = acc[mt][nt][1] + bv.y;
            v1.x = acc[mt][nt][2] + bv.x;
            v1.y = acc[mt][nt][3] + bv.y;
            *reinterpret_cast<float2*>(out + (size_t)mrow * DIM_N + ncol) = v0;
            *reinterpret_cast<float2*>(out + (size_t)(mrow + 8) * DIM_N + ncol) = v1;
        }
    }
}

// ---------------- host launch ----------------------------------------------
extern "C" void kernel_launch(void* const* d_in, const int* in_sizes, int n_in,
                              void* d_out, int out_size) {
    const float* x = (const float*)d_in[0];
    const float* W = (const float*)d_in[1];
    float* out = (float*)d_out;

    cudaFuncSetAttribute(kan_gemm_kernel, cudaFuncAttributeMaxDynamicSharedMemorySize,
                         SMEM_BYTES);

    prep_fused_kernel<<<NX_BLOCKS + NW_BLOCKS, 256>>>(x, W);
    kan_gemm_kernel<<<dim3(BATCH_M / BM, DIM_N / BN), NTHREADS, SMEM_BYTES>>>(out);
}

// round 17
// speedup vs baseline: 1.0783x; 1.0783x over previous
#include <cuda_runtime.h>
#include <cuda_fp16.h>
#include <cstdint>

// ============================================================================
// UniversalKANLinear: out[b,o] = sum_k (softplus(x[b,k])-ln2) * W[o,k]
//                              + (softplus(1)-ln2) * W[o,2048]
// B=8192, K=2048, N=2048.
// R17 == R16 resubmitted (R16 hit a GB300 container infra failure; no data).
//      GEMM = R6's best-measured config VERBATIM (128x128x64, 8 warps 64x32,
//      3-stage cp.async, 96KB, 2 CTAs/SM, unconditional commit). Mainloop
//      churn closed: five independent designs all plateau at tensor ~70%
//      => legacy-HMMA-pipe ceiling. Gains from prep: 4 outstanding float4
//      loads per thread (MLP=4) to lift prep_x off its latency bound.
// ============================================================================

#define BATCH_M 8192
#define DIM_K   2048
#define DIM_N   2048
#define W_COLS  2049

#define BM 128
#define BN 128
#define BK 64
#define KITERS (DIM_K / BK)     // 32
#define STAGES 3

// smem: rows of 64 fp16 = 128 B, XOR-swizzled in 16B chunks
#define A_STAGE_BYTES (BM * 128)                 // 16384
#define B_STAGE_BYTES (BN * 128)                 // 16384
#define STAGE_BYTES   (A_STAGE_BYTES + B_STAGE_BYTES)  // 32768
#define SMEM_BYTES    (STAGES * STAGE_BYTES)           // 98304

#define C_BIAS 0.62011450695827751f   // softplus(1) - ln2
#define LN2F   0.69314718055994531f

// prep grid layout
#define NX_BLOCKS 4096    // x: 4096 blocks x 256 thr x 4 float4 (MLP=4)
#define NW_BLOCKS 4096    // W: 4096 blocks x 256 thr x 4 scalars

// ---------------- scratch (device globals: allocation-free rule) -----------
__device__ __align__(1024) __half g_A[(size_t)BATCH_M * DIM_K];  // 32 MB phi(x)
__device__ __align__(1024) __half g_B[(size_t)DIM_N * DIM_K];    // 8 MB W
__device__ __align__(128)  float  g_bias[DIM_N];

// ---------------- helpers ---------------------------------------------------
__device__ __forceinline__ uint32_t smem_u32(const void* p) {
    uint32_t a;
    asm("{ .reg .u64 t; cvta.to.shared.u64 t, %1; cvt.u32.u64 %0, t; }" : "=r"(a) : "l"(p));
    return a;
}

#define CP_ASYNC16(dst_u32, src_ptr) \
    asm volatile("cp.async.cg.shared.global [%0], [%1], 16;" \
                 :: "r"(dst_u32), "l"(src_ptr) : "memory")
#define CP_COMMIT() asm volatile("cp.async.commit_group;" ::: "memory")
#define CP_WAIT(N)  asm volatile("cp.async.wait_group %0;" :: "n"(N) : "memory")

#define LDMATRIX_X4(r0, r1, r2, r3, addr) \
    asm volatile("ldmatrix.sync.aligned.m8n8.x4.shared.b16 {%0,%1,%2,%3}, [%4];" \
                 : "=r"(r0), "=r"(r1), "=r"(r2), "=r"(r3) : "r"(addr))

#define MMA_F16(c, a0, a1, a2, a3, b0, b1) \
    asm volatile("mma.sync.aligned.m16n8k16.row.col.f32.f16.f16.f32 " \
                 "{%0,%1,%2,%3}, {%4,%5,%6,%7}, {%8,%9}, {%0,%1,%2,%3};" \
                 : "+f"((c)[0]), "+f"((c)[1]), "+f"((c)[2]), "+f"((c)[3]) \
                 : "r"(a0), "r"(a1), "r"(a2), "r"(a3), "r"(b0), "r"(b1))

// ---------------- fused pre-pass kernel -------------------------------------
__device__ __forceinline__ float phi_f(float x) {
    float t = __expf(-fabsf(x));
    return fmaxf(x, 0.0f) + __logf(1.0f + t) - LN2F;
}

__device__ __forceinline__ uint2 phi_pack(float4 v) {
    __half2 h0 = __floats2half2_rn(phi_f(v.x), phi_f(v.y));
    __half2 h1 = __floats2half2_rn(phi_f(v.z), phi_f(v.w));
    uint2 p;
    p.x = *reinterpret_cast<uint32_t*>(&h0);
    p.y = *reinterpret_cast<uint32_t*>(&h1);
    return p;
}

__global__ void __launch_bounds__(256)
prep_fused_kernel(const float* __restrict__ x, const float* __restrict__ W) {
    const int b = blockIdx.x;
    const int tid = threadIdx.x;
    if (b < NX_BLOCKS) {
        // phi(x) -> g_A (fp16): 4 float4 per thread, ALL loads issued first
        size_t i = (size_t)b * 1024 + tid;
        const float4* src = reinterpret_cast<const float4*>(x);
        float4 v0 = src[i];
        float4 v1 = src[i + 256];
        float4 v2 = src[i + 512];
        float4 v3 = src[i + 768];
        uint2* dst = reinterpret_cast<uint2*>(g_A);
        dst[i]       = phi_pack(v0);
        dst[i + 256] = phi_pack(v1);
        dst[i + 512] = phi_pack(v2);
        dst[i + 768] = phi_pack(v3);
    } else {
        // W repack -> g_B (fp16), 4 consecutive k per thread
        const int wb = b - NX_BLOCKS;
        size_t base = (size_t)wb * 1024 + tid * 4;
        int o = (int)(base >> 11);
        int k = (int)(base & 2047);
        const float* wr = W + (size_t)o * W_COLS + k;
        float w0 = wr[0], w1 = wr[1], w2 = wr[2], w3 = wr[3];
        __half2 h0 = __floats2half2_rn(w0, w1);
        __half2 h1 = __floats2half2_rn(w2, w3);
        uint2 pack;
        pack.x = *reinterpret_cast<uint32_t*>(&h0);
        pack.y = *reinterpret_cast<uint32_t*>(&h1);
        *reinterpret_cast<uint2*>(g_B + base) = pack;
        if (wb == 0) {
            for (int o2 = tid; o2 < DIM_N; o2 += 256)
                g_bias[o2] = C_BIAS * W[(size_t)o2 * W_COLS + (W_COLS - 1)];
        }
    }
}

// ---------------- GEMM kernel (R6 verbatim) ---------------------------------
// smem addr for (row, 16B-chunk c16): row*128 + (c16 ^ (row&7))*16
__global__ void __launch_bounds__(256, 2)
kan_gemm_kernel(float* __restrict__ out) {
    extern __shared__ char smem[];
    const uint32_t sbase = smem_u32(smem);
    const int tid = threadIdx.x;
    const int lane = tid & 31;
    const int wid = tid >> 5;
    const int wm = wid & 1;        // 2 warp rows over BM=128 (64 each)
    const int wn = wid >> 1;       // 4 warp cols over BN=128 (32 each)
    const int m0 = blockIdx.x * BM;
    const int n0 = blockIdx.y * BN;
    const int r = lane >> 2;       // 0..7
    const int c = lane & 3;        // 0..3

    // ---- stage copy: A tile (128 rows x 128B) + B tile (128 rows x 128B) ----
    auto copy_stage = [&](int s, int kt) {
        const uint32_t sA = sbase + (uint32_t)s * STAGE_BYTES;
        const uint32_t sB = sA + A_STAGE_BYTES;
        const __half* gA = g_A + (size_t)m0 * DIM_K + (size_t)kt * BK;
        const __half* gB = g_B + (size_t)n0 * DIM_K + (size_t)kt * BK;
        #pragma unroll
        for (int i = 0; i < 4; i++) {            // A: 1024 16B chunks
            int v = tid + i * 256;
            int row = v >> 3, c16 = v & 7;
            CP_ASYNC16(sA + row * 128 + ((c16 ^ (row & 7)) * 16),
                       gA + (size_t)row * DIM_K + c16 * 8);
        }
        #pragma unroll
        for (int i = 0; i < 4; i++) {            // B: 1024 16B chunks
            int v = tid + i * 256;
            int row = v >> 3, c16 = v & 7;
            CP_ASYNC16(sB + row * 128 + ((c16 ^ (row & 7)) * 16),
                       gB + (size_t)row * DIM_K + c16 * 8);
        }
    };

    float acc[4][4][4];
    #pragma unroll
    for (int mt = 0; mt < 4; mt++)
        #pragma unroll
        for (int nt = 0; nt < 4; nt++)
            #pragma unroll
            for (int i = 0; i < 4; i++) acc[mt][nt][i] = 0.0f;

    copy_stage(0, 0); CP_COMMIT();
    copy_stage(1, 1); CP_COMMIT();

    // ldmatrix lane roles (loop-invariant)
    const int a_row = (lane & 15);                       // row within 16-row tile
    const int a_ch  = (lane >> 4);                       // k16 half (16B chunk)
    const int b_nrow = ((lane >> 4) << 3) + (lane & 7);  // 0-7 then 8-15
    const int b_ch  = (lane >> 3) & 1;                   // k-chunk within k16

    int rs = 0;  // read stage
    for (int kt = 0; kt < KITERS; kt++) {
        CP_WAIT(1);
        __syncthreads();
        if (kt + 2 < KITERS) copy_stage((kt + 2) % STAGES, kt + 2);
        CP_COMMIT();

        const uint32_t sA = sbase + (uint32_t)rs * STAGE_BYTES + (wm * 64) * 128;
        const uint32_t sB = sbase + (uint32_t)rs * STAGE_BYTES + A_STAGE_BYTES
                            + (wn * 32) * 128;

        #pragma unroll
        for (int ks = 0; ks < 4; ks++) {        // 4 x k16 steps over BK=64
            uint32_t a[4][4], b[2][4];
            #pragma unroll
            for (int mt = 0; mt < 4; mt++) {
                int row = mt * 16 + a_row;
                int ch = ks * 2 + a_ch;
                uint32_t addr = sA + row * 128 + ((ch ^ (row & 7)) * 16);
                LDMATRIX_X4(a[mt][0], a[mt][1], a[mt][2], a[mt][3], addr);
            }
            #pragma unroll
            for (int np = 0; np < 2; np++) {    // 2 x 16 n-rows = 32 cols
                int row = np * 16 + b_nrow;
                int ch = ks * 2 + b_ch;
                uint32_t addr = sB + row * 128 + ((ch ^ (row & 7)) * 16);
                LDMATRIX_X4(b[np][0], b[np][1], b[np][2], b[np][3], addr);
            }
            #pragma unroll
            for (int mt = 0; mt < 4; mt++) {
                #pragma unroll
                for (int np = 0; np < 2; np++) {
                    MMA_F16(acc[mt][2 * np],     a[mt][0], a[mt][1], a[mt][2], a[mt][3],
                            b[np][0], b[np][1]);
                    MMA_F16(acc[mt][2 * np + 1], a[mt][0], a[mt][1], a[mt][2], a[mt][3],
                            b[np][2], b[np][3]);
                }
            }
        }
        if (++rs == STAGES) rs = 0;
    }

    // ---- epilogue: acc + bias -> out ----
    const int mbase = m0 + wm * 64;
    const int nbase = n0 + wn * 32;
    #pragma unroll
    for (int mt = 0; mt < 4; mt++) {
        #pragma unroll
        for (int nt = 0; nt < 4; nt++) {
            int mrow = mbase + mt * 16 + r;
            int ncol = nbase + nt * 8 + 2 * c;
            float2 bv = *reinterpret_cast<const float2*>(g_bias + ncol);
            float2 v0, v1;
            v0.x = acc[mt][nt][0] + bv.x;
            v0.y = acc[mt][nt][1] + bv.y;
            v1.x = acc[mt][nt][2] + bv.x;
            v1.y = acc[mt][nt][3] + bv.y;
            *reinterpret_cast<float2*>(out + (size_t)mrow * DIM_N + ncol) = v0;
            *reinterpret_cast<float2*>(out + (size_t)(mrow + 8) * DIM_N + ncol) = v1;
        }
    }
}

// ---------------- host launch ----------------------------------------------
extern "C" void kernel_launch(void* const* d_in, const int* in_sizes, int n_in,
                              void* d_out, int out_size) {
    const float* x = (const float*)d_in[0];
    const float* W = (const float*)d_in[1];
    float* out = (float*)d_out;

    cudaFuncSetAttribute(kan_gemm_kernel, cudaFuncAttributeMaxDynamicSharedMemorySize,
                         SMEM_BYTES);

    prep_fused_kernel<<<NX_BLOCKS + NW_BLOCKS, 256>>>(x, W);
    kan_gemm_kernel<<<dim3(BATCH_M / BM, DIM_N / BN), 256, SMEM_BYTES>>>(out);
}